// round 14
// baseline (speedup 1.0000x reference)
#include <cuda_runtime.h>

#define BN   8
#define CN   64
#define HN   256
#define WN   256
#define HP   257
#define WP   257
#define HWN  (HN * WN)          // 65536
#define NPIX (HP * WP)          // 66049
#define LN_EPS 1e-5f
#define NEG_SLOPE 0.01f

// Padded channel-sum plane: cs(h,w) at [(h+3)*CST + (w+4)]. 262 rows
// (cs rows -3..258), stride 268 (cols -4..263). Border stays zero
// (zero-initialized globals; interior-only writes). Composed 6x6 stencil
// taps (rows/cols -3..+2) never leave the plane.
#define CROWS 262
#define CST   268
#define CPLANE (CROWS * CST)

#define NBLK  74                // blocks per image
#define NGRID (NBLK * BN)       // 592 = 4 * 148 SMs -> exact balanced wave
#define NTHR  256
#define CHUNK 893               // pixels per chunk (74*893 >= 66049)
#define Q4    (HWN / 4)         // 16384 float4 columns per image plane

// Scratch (static device globals — allowed)
__device__ float g_csp[BN * CPLANE];        // padded channel sum (~2.25 MB)
__device__ float g_part[BN * NBLK * 2];     // per-block (sum, sumsq)
__device__ unsigned int g_done[BN * NBLK];  // per-block chansum epoch flags.
                                            // Monotone: +1 per launch; all
                                            // equal at launch start => the
                                            // waiter's own post-increment value
                                            // is the correct target (replay-safe)
__device__ unsigned int g_tkt[BN * 32];     // per-image partials counters, 128B
                                            // apart; monotone +NBLK per launch

// ---------------------------------------------------------------------------
// One persistent kernel:
//   image-local chansum (full-depth loops, no intra-phase syncs)
//   -> publish per-block done flag
//   -> wait ONLY on the <=7 producer blocks covering this block's tile rows
//   -> 36-tap composed stencil (+ LN partials)
//   -> per-image ticket barrier
//   -> stats + normalize + LeakyReLU
// ---------------------------------------------------------------------------
__global__ void __launch_bounds__(NTHR, 4)
k_all(const float* __restrict__ x, const float* __restrict__ cw,
      const float* __restrict__ cb, float* __restrict__ out) {
    __shared__ float s_c6[36];                // composed 6x6 stencil coeffs
    __shared__ float s_tile[10 * CST];        // 10 padded rows (10.5 KB)
    __shared__ float s_red[8][2];

    const int tid = threadIdx.x;
    const int blk = blockIdx.x;
    const int b   = blk / NBLK;               // this block's image
    const int xb  = blk - b * NBLK;           // index within image [0,74)

    // ---- Phase 0: channel sum for image b (image-local column slice) ----
    {
        unsigned base = ((unsigned)xb * Q4) / NBLK;
        unsigned end  = ((unsigned)(xb + 1) * Q4) / NBLK;
        unsigned col  = base + (unsigned)tid;
        if (col < end) {
            const float4* xp = reinterpret_cast<const float4*>(x)
                               + (size_t)b * CN * Q4 + col;
            float ax = 0.f, ay = 0.f, az = 0.f, aw = 0.f;
#pragma unroll
            for (int cc = 0; cc < CN; cc += 8) {
                float4 buf[8];
#pragma unroll
                for (int i = 0; i < 8; ++i)
                    buf[i] = __ldcs(xp + (size_t)(cc + i) * Q4);
#pragma unroll
                for (int i = 0; i < 8; ++i) {
                    ax += buf[i].x; ay += buf[i].y; az += buf[i].z; aw += buf[i].w;
                }
            }
            int p = (int)col * 4;
            int h = p >> 8, w = p & 255;
            *reinterpret_cast<float4*>(
                g_csp + (size_t)b * CPLANE + (h + 3) * CST + (w + 4)) =
                make_float4(ax, ay, az, aw);
        }
    }

    // ---- Composed coefficients: pool(2) o 16-tap shift stencil = 6x6 ----
    if (tid < 36) {
        const signed char tdr[16] = {2,-2, 2,-2, 2,-2, 2,-2, 2,-2, 1,-1, 0,0, -1,1};
        const signed char tdc[16] = {2,-2, 1,-1, 0, 0,-1, 1,-2, 2,-2, 2,-2,2, -2,2};
        const signed char twi[16] = {0, 0, 1, 1, 2, 2, 3, 3, 4, 4, 5, 5, 6,6,  7,7};
        const signed char tsg[16] = {1,-1, 1,-1, 1,-1, 1,-1, 1,-1, 1,-1, 1,-1, 1,-1};
        int r = tid / 6 - 3, c = tid % 6 - 3;
        float acc = 0.f;
        for (int t2 = 0; t2 < 16; ++t2) {
            int ur = r - tdr[t2], uc = c - tdc[t2];
            if ((ur == 0 || ur == -1) && (uc == 0 || uc == -1))
                acc += (float)tsg[t2] * cw[twi[t2]];
        }
        s_c6[tid] = 0.25f * acc;
    }

    // ---- Publish done flag; wait only on this tile's producer blocks ----
    const int p0   = xb * CHUNK;
    const int pend = (p0 + CHUNK < NPIX) ? p0 + CHUNK : NPIX;
    const int h0   = p0 / WP;                 // first output row of this chunk

    __syncthreads();                          // chansum stores + s_c6 done
    if (tid == 0) {
        __threadfence();                      // publish plane stores
        unsigned epoch = atomicAdd(&g_done[b * NBLK + xb], 1u) + 1u;

        // Tile needs padded rows h0..h0+9 = cs rows (h0-3)..(h0+6), clamped.
        int r_lo = h0 - 3; if (r_lo < 0) r_lo = 0;
        int r_hi = h0 + 6; if (r_hi > HN - 1) r_hi = HN - 1;
        // cs row r is produced by float4 cols [64r, 64r+63]. Block j covers
        // cols [j*Q4/74, (j+1)*Q4/74). Conservative +-1 padding on the range.
        int j_lo = (int)(((long)r_lo * 64 * NBLK) / Q4) - 1;
        int j_hi = (int)((((long)r_hi * 64 + 63) * NBLK) / Q4) + 1;
        if (j_lo < 0) j_lo = 0;
        if (j_hi > NBLK - 1) j_hi = NBLK - 1;
        for (int j = j_lo; j <= j_hi; ++j) {
            volatile unsigned* f = &g_done[b * NBLK + j];
            while (*f < epoch) __nanosleep(32);
        }
    }
    __syncthreads();
    __threadfence();                          // acquire producers' stores

    // ---- Phase B: 36-tap stencil from smem tile (4 strided px/thread) ----
    const float* __restrict__ plane = g_csp + (size_t)b * CPLANE;
    for (int i4 = tid; i4 < 10 * (CST / 4); i4 += NTHR) {
        int r  = i4 / (CST / 4);
        int c4 = i4 - r * (CST / 4);
        int pr = h0 + r;
        float4 v = make_float4(0.f, 0.f, 0.f, 0.f);
        if (pr < CROWS)
            v = *(reinterpret_cast<const float4*>(plane + (size_t)pr * CST) + c4);
        reinterpret_cast<float4*>(s_tile)[r * (CST / 4) + c4] = v;
    }
    __syncthreads();

    const float bias = __ldg(cb);
    float vv[4] = {bias, bias, bias, bias};
    float lsum = 0.f, lsq = 0.f;
    const int pbase = p0 + tid;
    {
        int hh[4], jj[4];
#pragma unroll
        for (int k = 0; k < 4; ++k) {
            int p = pbase + k * 256;
            int h = p / WP;
            hh[k] = h; jj[k] = p - h * WP;
        }
        if (pend - p0 == CHUNK && pbase + 3 * 256 < pend) {
            // fast path: all 4 pixels valid (73 of 74 chunks)
#pragma unroll
            for (int r = 0; r < 6; ++r)
#pragma unroll
                for (int c = 0; c < 6; ++c) {
                    float cf = s_c6[r * 6 + c];
#pragma unroll
                    for (int k = 0; k < 4; ++k)
                        vv[k] = fmaf(cf,
                                     s_tile[(hh[k] - h0 + r) * CST + jj[k] + 1 + c],
                                     vv[k]);
                }
#pragma unroll
            for (int k = 0; k < 4; ++k) { lsum += vv[k]; lsq += vv[k] * vv[k]; }
        } else {
            bool ok[4];
#pragma unroll
            for (int k = 0; k < 4; ++k) ok[k] = (pbase + k * 256) < pend;
#pragma unroll
            for (int r = 0; r < 6; ++r)
#pragma unroll
                for (int c = 0; c < 6; ++c) {
                    float cf = s_c6[r * 6 + c];
#pragma unroll
                    for (int k = 0; k < 4; ++k)
                        if (ok[k])
                            vv[k] = fmaf(cf,
                                s_tile[(hh[k] - h0 + r) * CST + jj[k] + 1 + c],
                                vv[k]);
                }
#pragma unroll
            for (int k = 0; k < 4; ++k)
                if (ok[k]) { lsum += vv[k]; lsq += vv[k] * vv[k]; }
        }
    }

    // Deterministic block reduction
#pragma unroll
    for (int o = 16; o > 0; o >>= 1) {
        lsum += __shfl_down_sync(0xffffffffu, lsum, o);
        lsq  += __shfl_down_sync(0xffffffffu, lsq,  o);
    }
    int wid = tid >> 5, lane = tid & 31;
    if (lane == 0) { s_red[wid][0] = lsum; s_red[wid][1] = lsq; }
    __syncthreads();
    if (tid == 0) {
        float a = 0.f, q = 0.f;
#pragma unroll
        for (int w = 0; w < 8; ++w) { a += s_red[w][0]; q += s_red[w][1]; }
        g_part[(b * NBLK + xb) * 2 + 0] = a;
        g_part[(b * NBLK + xb) * 2 + 1] = q;
        __threadfence();                      // publish partials
        unsigned* c = &g_tkt[b * 32];
        unsigned t = atomicAdd(c, 1u) + 1u;
        unsigned target = ((t + NBLK - 1u) / NBLK) * NBLK;
        volatile unsigned* vc = c;
        while (*vc < target) __nanosleep(32);
    }
    __syncthreads();
    __threadfence();                          // acquire peers' partials

    // ---- Phase C: redundant deterministic stats + normalize + LeakyReLU ----
    const float* __restrict__ part = g_part + b * NBLK * 2;
    float a = 0.f, q = 0.f;
#pragma unroll
    for (int i = 0; i < NBLK; ++i) {
        a += part[i * 2 + 0];
        q += part[i * 2 + 1];
    }
    const float inv_n = 1.0f / (float)NPIX;
    const float mean = a * inv_n;
    const float istd = rsqrtf(q * inv_n - mean * mean + LN_EPS);

    float* __restrict__ o = out + (size_t)b * NPIX;
#pragma unroll
    for (int k = 0; k < 4; ++k) {
        int p = pbase + k * 256;
        if (p < pend) {
            float v = (vv[k] - mean) * istd;
            o[p] = v >= 0.f ? v : NEG_SLOPE * v;
        }
    }
}

// ---------------------------------------------------------------------------

extern "C" void kernel_launch(void* const* d_in, const int* in_sizes, int n_in,
                              void* d_out, int out_size) {
    const float* x  = (const float*)d_in[0];   // [8,64,256,256]
    const float* cw = (const float*)d_in[1];   // [1,8]
    const float* cb = (const float*)d_in[2];   // [1]
    float* out = (float*)d_out;                // [8,1,257,257]
    (void)in_sizes; (void)n_in; (void)out_size;

    k_all<<<NGRID, NTHR>>>(x, cw, cb, out);
}

// round 15
// speedup vs baseline: 1.0242x; 1.0242x over previous
#include <cuda_runtime.h>

#define BN   8
#define CN   64
#define HN   256
#define WN   256
#define HP   257
#define WP   257
#define HWN  (HN * WN)          // 65536
#define NPIX (HP * WP)          // 66049
#define LN_EPS 1e-5f
#define NEG_SLOPE 0.01f

// Padded channel-sum plane: cs(h,w) at [(h+3)*CST + (w+4)]. 262 rows
// (cs rows -3..258), stride 268 (cols -4..263). Border stays zero
// (zero-initialized globals; interior-only writes). Composed 6x6 stencil
// taps (rows/cols -3..+2) never leave the plane.
#define CROWS 262
#define CST   268
#define CPLANE (CROWS * CST)

#define NBLK  74                // blocks per image
#define NGRID (NBLK * BN)       // 592 = 4 * 148 SMs -> exact balanced wave
#define NTHR  256
#define CHUNK 893               // output pixels per block (74*893 >= 66049)
#define Q4    (HWN / 4)         // 16384 float4 columns per image plane

#define NCHUNK 128              // chansum chunks per image
#define CHCOLS 128              // float4 columns per chunk (128*128 = Q4)

// Scratch (static device globals — allowed)
__device__ float g_csp[BN * CPLANE];       // padded channel sum (~2.25 MB)
__device__ float g_part[BN * NBLK * 2];    // per-block (sum, sumsq)
__device__ unsigned int g_tkt[BN * 32];    // per-image barrier counters, 128B
                                           // apart; monotone +2*NBLK/launch
__device__ unsigned int g_q[BN * 32];      // per-image chansum work queues;
                                           // grab-with-restore nets exactly
                                           // +NCHUNK per launch (replay-safe)

// ---------------------------------------------------------------------------
// Per-image ticket barrier (R13): only the 74 blocks of one image sync.
// Exact single wave (592 = 4*148, launch_bounds(256,4)) => spin is safe.
// ---------------------------------------------------------------------------
__device__ __forceinline__ void img_barrier(int tid, int b) {
    __syncthreads();
    if (tid == 0) {
        __threadfence();                              // publish this block's stores
        unsigned* c = &g_tkt[b * 32];
        unsigned t = atomicAdd(c, 1u) + 1u;
        unsigned target = ((t + NBLK - 1u) / NBLK) * NBLK;
        volatile unsigned* vc = c;
        while (*vc < target) __nanosleep(32);
    }
    __syncthreads();
    __threadfence();                                  // acquire peers' stores
}

// ---------------------------------------------------------------------------
// One persistent kernel: work-stolen chansum -> per-image barrier -> 36-tap
// composed stencil (+ LN partials) -> per-image barrier -> stats + norm.
// ---------------------------------------------------------------------------
__global__ void __launch_bounds__(NTHR, 4)
k_all(const float* __restrict__ x, const float* __restrict__ cw,
      const float* __restrict__ cb, float* __restrict__ out) {
    __shared__ float s_c6[36];                // composed 6x6 stencil coeffs
    __shared__ float s_tile[10 * CST];        // 10 padded rows (10.5 KB)
    __shared__ float s_red[8][2];
    __shared__ float4 s_acc[CHCOLS];          // chunk half-combine (2 KB)
    __shared__ unsigned s_epoch, s_chunk;

    const int tid = threadIdx.x;
    const int blk = blockIdx.x;
    const int b   = blk / NBLK;               // this block's image
    const int xb  = blk - b * NBLK;           // index within image [0,74)

    // ---- Epoch read (before any same-image g_tkt increment can happen:
    //      increments require all image-b blocks to finish phase 0, which is
    //      after all their epoch reads; transient +k (k<148) floors safely) ----
    if (tid == 0) s_epoch = g_tkt[b * 32] / (2u * NBLK);

    // ---- Composed coefficients: pool(2) o 16-tap shift stencil = 6x6 ----
    if (tid < 36) {
        const signed char tdr[16] = {2,-2, 2,-2, 2,-2, 2,-2, 2,-2, 1,-1, 0,0, -1,1};
        const signed char tdc[16] = {2,-2, 1,-1, 0, 0,-1, 1,-2, 2,-2, 2,-2,2, -2,2};
        const signed char twi[16] = {0, 0, 1, 1, 2, 2, 3, 3, 4, 4, 5, 5, 6,6,  7,7};
        const signed char tsg[16] = {1,-1, 1,-1, 1,-1, 1,-1, 1,-1, 1,-1, 1,-1, 1,-1};
        int r = tid / 6 - 3, c = tid % 6 - 3;
        float acc = 0.f;
        for (int t2 = 0; t2 < 16; ++t2) {
            int ur = r - tdr[t2], uc = c - tdc[t2];
            if ((ur == 0 || ur == -1) && (uc == 0 || uc == -1))
                acc += (float)tsg[t2] * cw[twi[t2]];
        }
        s_c6[tid] = 0.25f * acc;
    }
    __syncthreads();

    // ---- Phase 0: chansum via per-image dynamic chunk queue ----
    // Chunk c covers float4 columns [c*128, (c+1)*128). Threads: 128 columns
    // x 2 channel-halves (32 channels each, 8-deep batched loads).
    {
        const unsigned qbase = s_epoch * NCHUNK;
        const unsigned limit = qbase + NCHUNK;
        const int ccol = tid & (CHCOLS - 1);
        const int half = tid >> 7;            // 0: ch 0-31, 1: ch 32-63
        for (;;) {
            if (tid == 0) {
                unsigned t = atomicAdd(&g_q[b * 32], 1u);
                if (t >= limit) {             // overshoot: restore & exit
                    atomicSub(&g_q[b * 32], 1u);
                    t = 0xFFFFFFFFu;
                }
                s_chunk = t;
            }
            __syncthreads();
            unsigned t = s_chunk;
            if (t == 0xFFFFFFFFu) break;
            int c = (int)(t - qbase);
            int col = c * CHCOLS + ccol;

            const float4* xp = reinterpret_cast<const float4*>(x)
                               + ((size_t)b * CN + (size_t)half * 32) * Q4 + col;
            float ax = 0.f, ay = 0.f, az = 0.f, aw = 0.f;
#pragma unroll
            for (int cc = 0; cc < 32; cc += 8) {
                float4 buf[8];
#pragma unroll
                for (int i = 0; i < 8; ++i)
                    buf[i] = __ldcs(xp + (size_t)(cc + i) * Q4);
#pragma unroll
                for (int i = 0; i < 8; ++i) {
                    ax += buf[i].x; ay += buf[i].y; az += buf[i].z; aw += buf[i].w;
                }
            }
            if (half == 1) s_acc[ccol] = make_float4(ax, ay, az, aw);
            __syncthreads();
            if (half == 0) {                  // fixed combine order: deterministic
                float4 o4 = s_acc[ccol];
                o4.x += ax; o4.y += ay; o4.z += az; o4.w += aw;
                int p = col * 4;
                int h = p >> 8, w = p & 255;
                *reinterpret_cast<float4*>(
                    g_csp + (size_t)b * CPLANE + (h + 3) * CST + (w + 4)) = o4;
            }
            __syncthreads();                  // s_acc reusable next iteration
        }
    }

    img_barrier(tid, b);                      // image b's cs plane ready

    // ---- Phase B: 36-tap stencil from smem tile (893-px chunk, 4 strided
    //      pixels per thread) — identical to R13 ----
    const int p0   = xb * CHUNK;
    const int pend = (p0 + CHUNK < NPIX) ? p0 + CHUNK : NPIX;
    const int h0   = p0 / WP;                 // first output row of this chunk
    const float* __restrict__ plane = g_csp + (size_t)b * CPLANE;

    for (int i4 = tid; i4 < 10 * (CST / 4); i4 += NTHR) {
        int r  = i4 / (CST / 4);
        int c4 = i4 - r * (CST / 4);
        int pr = h0 + r;
        float4 v = make_float4(0.f, 0.f, 0.f, 0.f);
        if (pr < CROWS)
            v = *(reinterpret_cast<const float4*>(plane + (size_t)pr * CST) + c4);
        reinterpret_cast<float4*>(s_tile)[r * (CST / 4) + c4] = v;
    }
    __syncthreads();

    const float bias = __ldg(cb);
    float vv[4] = {0.f, 0.f, 0.f, 0.f};
    float lsum = 0.f, lsq = 0.f;
    const int pbase = p0 + tid;
    {
        int  hh[4], jj[4];
        bool ok[4];
#pragma unroll
        for (int k = 0; k < 4; ++k) {
            int p = pbase + k * 256;
            ok[k] = p < pend;
            int h = p / WP;
            hh[k] = h; jj[k] = p - h * WP;
            vv[k] = bias;
        }
#pragma unroll
        for (int r = 0; r < 6; ++r) {
#pragma unroll
            for (int c = 0; c < 6; ++c) {
                float cf = s_c6[r * 6 + c];
#pragma unroll
                for (int k = 0; k < 4; ++k)
                    if (ok[k])
                        vv[k] = fmaf(cf,
                                     s_tile[(hh[k] - h0 + r) * CST + jj[k] + 1 + c],
                                     vv[k]);
            }
        }
#pragma unroll
        for (int k = 0; k < 4; ++k)
            if (ok[k]) { lsum += vv[k]; lsq += vv[k] * vv[k]; }
    }

    // Deterministic block reduction
#pragma unroll
    for (int o = 16; o > 0; o >>= 1) {
        lsum += __shfl_down_sync(0xffffffffu, lsum, o);
        lsq  += __shfl_down_sync(0xffffffffu, lsq,  o);
    }
    int wid = tid >> 5, lane = tid & 31;
    if (lane == 0) { s_red[wid][0] = lsum; s_red[wid][1] = lsq; }
    __syncthreads();
    if (tid == 0) {
        float a = 0.f, q = 0.f;
#pragma unroll
        for (int w = 0; w < 8; ++w) { a += s_red[w][0]; q += s_red[w][1]; }
        g_part[(b * NBLK + xb) * 2 + 0] = a;
        g_part[(b * NBLK + xb) * 2 + 1] = q;
    }

    img_barrier(tid, b);                      // image b's partials ready

    // ---- Phase C: redundant deterministic stats + normalize + LeakyReLU ----
    const float* __restrict__ part = g_part + b * NBLK * 2;
    float a = 0.f, q = 0.f;
#pragma unroll
    for (int i = 0; i < NBLK; ++i) {
        a += part[i * 2 + 0];
        q += part[i * 2 + 1];
    }
    const float inv_n = 1.0f / (float)NPIX;
    const float mean = a * inv_n;
    const float istd = rsqrtf(q * inv_n - mean * mean + LN_EPS);

    float* __restrict__ o = out + (size_t)b * NPIX;
#pragma unroll
    for (int k = 0; k < 4; ++k) {
        int p = pbase + k * 256;
        if (p < pend) {
            float v = (vv[k] - mean) * istd;
            o[p] = v >= 0.f ? v : NEG_SLOPE * v;
        }
    }
}

// ---------------------------------------------------------------------------

extern "C" void kernel_launch(void* const* d_in, const int* in_sizes, int n_in,
                              void* d_out, int out_size) {
    const float* x  = (const float*)d_in[0];   // [8,64,256,256]
    const float* cw = (const float*)d_in[1];   // [1,8]
    const float* cb = (const float*)d_in[2];   // [1]
    float* out = (float*)d_out;                // [8,1,257,257]
    (void)in_sizes; (void)n_in; (void)out_size;

    k_all<<<NGRID, NTHR>>>(x, cw, cb, out);
}

// round 16
// speedup vs baseline: 1.0912x; 1.0654x over previous
#include <cuda_runtime.h>

#define BN   8
#define CN   64
#define HN   256
#define WN   256
#define HP   257
#define WP   257
#define HWN  (HN * WN)          // 65536
#define NPIX (HP * WP)          // 66049
#define LN_EPS 1e-5f
#define NEG_SLOPE 0.01f

// Padded channel-sum plane: cs(h,w) at [(h+3)*CST + (w+4)]. 262 rows
// (cs rows -3..258), stride 268 (cols -4..263). Border stays zero
// (zero-initialized globals; interior-only writes). Composed 6x6 stencil
// taps (rows/cols -3..+2) never leave the plane.
#define CROWS 262
#define CST   268
#define CST4  (CST / 4)         // 67
#define CPLANE (CROWS * CST)

#define NBLK  65                // blocks per image (4 output rows each)
#define NGRID (NBLK * BN)       // 520 blocks, single resident wave
#define NTHR  256
#define Q4    (HWN / 4)         // 16384 float4 columns per image plane

// Scratch (static device globals — allowed)
__device__ float g_csp[BN * CPLANE];       // padded channel sum (~2.25 MB)
__device__ float g_part[BN * NBLK * 2];    // per-block (sum, sumsq)
__device__ unsigned int g_tkt[BN * 32];    // per-image ticket counters, 128B
                                           // apart; monotone (+2*NBLK per
                                           // launch -> multiple of NBLK at
                                           // every launch start: replay-safe)

// ---------------------------------------------------------------------------
// Per-image ticket barrier: only the 65 blocks of one image synchronize.
// Single resident wave (520 <= 4*148, launch_bounds(256,4)) => spin safe.
// ---------------------------------------------------------------------------
__device__ __forceinline__ void img_barrier(int tid, int b) {
    __syncthreads();
    if (tid == 0) {
        __threadfence();                              // publish this block's stores
        unsigned* c = &g_tkt[b * 32];
        unsigned t = atomicAdd(c, 1u) + 1u;
        unsigned target = ((t + NBLK - 1u) / NBLK) * NBLK;
        volatile unsigned* vc = c;
        while (*vc < target) __nanosleep(32);
    }
    __syncthreads();
    __threadfence();                                  // acquire peers' stores
}

// ---------------------------------------------------------------------------
// One persistent kernel: image-local chansum (full-depth loops, no intra-
// phase syncs) -> per-image barrier -> 36-tap composed stencil with
// VERTICAL 4-pixel tiling (54 LDS / 4 px instead of 144) -> per-image
// barrier -> stats + normalize + LeakyReLU.
// ---------------------------------------------------------------------------
__global__ void __launch_bounds__(NTHR, 4)
k_all(const float* __restrict__ x, const float* __restrict__ cw,
      const float* __restrict__ cb, float* __restrict__ out) {
    __shared__ float s_c6[36];                // composed 6x6 stencil coeffs
    __shared__ float s_tile[9 * CST];         // 9 padded rows (9.4 KB)
    __shared__ float s_red[8][2];

    const int tid = threadIdx.x;
    const int blk = blockIdx.x;
    const int b   = blk / NBLK;               // this block's image
    const int xb  = blk - b * NBLK;           // index within image [0,65)

    // ---- Phase 0: channel sum for image b (image-local column slice) ----
    // Block xb handles float4 columns [xb*Q4/65, (xb+1)*Q4/65): 252-253
    // columns, one per thread, 64 channels deep, 8-deep load batching.
    {
        unsigned base = ((unsigned)xb * Q4) / NBLK;
        unsigned end  = ((unsigned)(xb + 1) * Q4) / NBLK;
        unsigned col  = base + (unsigned)tid;
        if (col < end) {
            const float4* xp = reinterpret_cast<const float4*>(x)
                               + (size_t)b * CN * Q4 + col;
            float ax = 0.f, ay = 0.f, az = 0.f, aw = 0.f;
#pragma unroll
            for (int cc = 0; cc < CN; cc += 8) {
                float4 buf[8];
#pragma unroll
                for (int i = 0; i < 8; ++i)
                    buf[i] = __ldcs(xp + (size_t)(cc + i) * Q4);
#pragma unroll
                for (int i = 0; i < 8; ++i) {
                    ax += buf[i].x; ay += buf[i].y; az += buf[i].z; aw += buf[i].w;
                }
            }
            int p = (int)col * 4;
            int h = p >> 8, w = p & 255;
            *reinterpret_cast<float4*>(
                g_csp + (size_t)b * CPLANE + (h + 3) * CST + (w + 4)) =
                make_float4(ax, ay, az, aw);
        }
    }

    // ---- Composed coefficients: pool(2) o 16-tap shift stencil = 6x6 ----
    if (tid < 36) {
        const signed char tdr[16] = {2,-2, 2,-2, 2,-2, 2,-2, 2,-2, 1,-1, 0,0, -1,1};
        const signed char tdc[16] = {2,-2, 1,-1, 0, 0,-1, 1,-2, 2,-2, 2,-2,2, -2,2};
        const signed char twi[16] = {0, 0, 1, 1, 2, 2, 3, 3, 4, 4, 5, 5, 6,6,  7,7};
        const signed char tsg[16] = {1,-1, 1,-1, 1,-1, 1,-1, 1,-1, 1,-1, 1,-1, 1,-1};
        int r = tid / 6 - 3, c = tid % 6 - 3;
        float acc = 0.f;
        for (int t2 = 0; t2 < 16; ++t2) {
            int ur = r - tdr[t2], uc = c - tdc[t2];
            if ((ur == 0 || ur == -1) && (uc == 0 || uc == -1))
                acc += (float)tsg[t2] * cw[twi[t2]];
        }
        s_c6[tid] = 0.25f * acc;
    }

    img_barrier(tid, b);                      // image b's cs plane ready

    // ---- Phase B: vertical 4-pixel stencil ----
    // Block covers output rows r0..r0+3, all 257 columns. Thread tid owns
    // column tid, rows r0..r0+3; threads 252-255 also own one pixel each of
    // column 256 (row r0 + (tid-252)).
    const int r0 = xb * 4;
    const int nr = (HP - r0 < 4) ? (HP - r0) : 4;     // valid rows (4, or 1)
    const float* __restrict__ plane = g_csp + (size_t)b * CPLANE;

    // Tile = padded rows r0..r0+8 (tile row 0 = cs row r0-3). Covers the
    // 6-row windows of all 4 output rows. Bounds only matter for xb=64.
    for (int i4 = tid; i4 < 9 * CST4; i4 += NTHR) {
        int r  = i4 / CST4;
        int c4 = i4 - r * CST4;
        int pr = r0 + r;
        float4 v = make_float4(0.f, 0.f, 0.f, 0.f);
        if (pr < CROWS)
            v = *(reinterpret_cast<const float4*>(plane + (size_t)pr * CST) + c4);
        reinterpret_cast<float4*>(s_tile)[i4] = v;
    }
    __syncthreads();

    const float bias = __ldg(cb);
    float acc[4] = {bias, bias, bias, bias};
    float vx = bias;                          // extra col-256 pixel (tid>=252)
    float lsum = 0.f, lsq = 0.f;

    {
        // Pixel (r0+k, tid): taps s_tile[(k+r)*CST + tid+1+c], r,c in [0,6).
        // Column-wise: 9 loads feed 24 FMAs. No predicates (cols always valid).
        const float* tb = s_tile + tid + 1;
#pragma unroll
        for (int c = 0; c < 6; ++c) {
            float t[9];
#pragma unroll
            for (int r = 0; r < 9; ++r) t[r] = tb[r * CST + c];
#pragma unroll
            for (int r = 0; r < 6; ++r) {
                float cf = s_c6[r * 6 + c];
#pragma unroll
                for (int k = 0; k < 4; ++k)
                    acc[k] = fmaf(cf, t[k + r], acc[k]);
            }
        }
#pragma unroll
        for (int k = 0; k < 4; ++k)
            if (k < nr) { lsum += acc[k]; lsq += acc[k] * acc[k]; }

        // Extra pixels: col 256, rows r0..r0+3 on threads 252..255.
        if (tid >= 252) {
            int k2 = tid - 252;
            if (k2 < nr) {
                const float* tb2 = s_tile + 257;
#pragma unroll
                for (int r = 0; r < 6; ++r)
#pragma unroll
                    for (int c = 0; c < 6; ++c)
                        vx = fmaf(s_c6[r * 6 + c], tb2[(k2 + r) * CST + c], vx);
                lsum += vx; lsq += vx * vx;
            }
        }
    }

    // Deterministic block reduction
#pragma unroll
    for (int o = 16; o > 0; o >>= 1) {
        lsum += __shfl_down_sync(0xffffffffu, lsum, o);
        lsq  += __shfl_down_sync(0xffffffffu, lsq,  o);
    }
    int wid = tid >> 5, lane = tid & 31;
    if (lane == 0) { s_red[wid][0] = lsum; s_red[wid][1] = lsq; }
    __syncthreads();
    if (tid == 0) {
        float a = 0.f, q = 0.f;
#pragma unroll
        for (int w = 0; w < 8; ++w) { a += s_red[w][0]; q += s_red[w][1]; }
        g_part[(b * NBLK + xb) * 2 + 0] = a;
        g_part[(b * NBLK + xb) * 2 + 1] = q;
    }

    img_barrier(tid, b);                      // image b's partials ready

    // ---- Phase C: redundant deterministic stats + normalize + LeakyReLU ----
    const float* __restrict__ part = g_part + b * NBLK * 2;
    float a = 0.f, q = 0.f;
#pragma unroll
    for (int i = 0; i < NBLK; ++i) {
        a += part[i * 2 + 0];
        q += part[i * 2 + 1];
    }
    const float inv_n = 1.0f / (float)NPIX;
    const float mean = a * inv_n;
    const float istd = rsqrtf(q * inv_n - mean * mean + LN_EPS);

    float* __restrict__ o = out + (size_t)b * NPIX;
#pragma unroll
    for (int k = 0; k < 4; ++k) {
        if (k < nr) {
            float v = (acc[k] - mean) * istd;
            o[(r0 + k) * WP + tid] = v >= 0.f ? v : NEG_SLOPE * v;
        }
    }
    if (tid >= 252) {
        int k2 = tid - 252;
        if (k2 < nr) {
            float v = (vx - mean) * istd;
            o[(r0 + k2) * WP + 256] = v >= 0.f ? v : NEG_SLOPE * v;
        }
    }
}

// ---------------------------------------------------------------------------

extern "C" void kernel_launch(void* const* d_in, const int* in_sizes, int n_in,
                              void* d_out, int out_size) {
    const float* x  = (const float*)d_in[0];   // [8,64,256,256]
    const float* cw = (const float*)d_in[1];   // [1,8]
    const float* cb = (const float*)d_in[2];   // [1]
    float* out = (float*)d_out;                // [8,1,257,257]
    (void)in_sizes; (void)n_in; (void)out_size;

    k_all<<<NGRID, NTHR>>>(x, cw, cb, out);
}